// round 1
// baseline (speedup 1.0000x reference)
#include <cuda_runtime.h>

#define B_ 8
#define S_ 2048
#define D_ 1024
#define H_ 64
#define M_ (B_*S_)

// Scratch for projected q, k, v ([B*S, H] row-major each)
__device__ float g_q[M_*H_];
__device__ float g_k[M_*H_];
__device__ float g_v[M_*H_];

// ---------------------------------------------------------------------------
// Kernel 1: fused QKV projection.
//   q/k/v[m, h] = sum_d x[m, d] * W{q,k,v}[d, h]
// 64 rows per block, 256 threads (16x16). Each thread: 4 rows x 12 cols of the
// concatenated [q|k|v] 192-wide output. K dimension streamed in chunks of 32.
// ---------------------------------------------------------------------------
__global__ __launch_bounds__(256) void proj_kernel(
    const float* __restrict__ x,
    const float* __restrict__ Wq,
    const float* __restrict__ Wk,
    const float* __restrict__ Wv)
{
    __shared__ float xs[64][36];    // 64 rows x 32 k (+pad, 16B-aligned rows)
    __shared__ float ws[32][196];   // 32 k x 192 cols (+pad to 49 float4)

    const int t  = threadIdx.x;
    const int tx = t & 15;
    const int ty = t >> 4;
    const int m0 = blockIdx.x * 64;

    float acc[4][12];
#pragma unroll
    for (int i = 0; i < 4; i++)
#pragma unroll
        for (int j = 0; j < 12; j++) acc[i][j] = 0.f;

    for (int kk = 0; kk < D_; kk += 32) {
        __syncthreads();
        // Load x tile: 64 rows x 32 cols as float4 (coalesced)
#pragma unroll
        for (int i = 0; i < 2; i++) {
            int f = t + 256 * i;            // float4 index over [64][8]
            int r = f >> 3, kq = f & 7;
            float4 v = *(const float4*)(x + (m0 + r) * D_ + kk + kq * 4);
            *(float4*)(&xs[r][kq * 4]) = v;
        }
        // Load weight chunks: 3 x (32 x 64) floats into ws[k][mat*64 + h]
        const float* Wm[3] = {Wq, Wk, Wv};
#pragma unroll
        for (int m = 0; m < 3; m++) {
#pragma unroll
            for (int i = 0; i < 2; i++) {
                int f = t + 256 * i;        // float4 index over [32][16]
                int r = f >> 4, hq = f & 15;
                float4 v = *(const float4*)(Wm[m] + (kk + r) * H_ + hq * 4);
                *(float4*)(&ws[r][m * 64 + hq * 4]) = v;
            }
        }
        __syncthreads();

#pragma unroll 4
        for (int k = 0; k < 32; k++) {
            float a[4];
#pragma unroll
            for (int i = 0; i < 4; i++) a[i] = xs[ty * 4 + i][k];
            float4 b0 = *(const float4*)(&ws[k][tx * 12]);
            float4 b1 = *(const float4*)(&ws[k][tx * 12 + 4]);
            float4 b2 = *(const float4*)(&ws[k][tx * 12 + 8]);
            float b[12] = {b0.x, b0.y, b0.z, b0.w,
                           b1.x, b1.y, b1.z, b1.w,
                           b2.x, b2.y, b2.z, b2.w};
#pragma unroll
            for (int i = 0; i < 4; i++)
#pragma unroll
                for (int j = 0; j < 12; j++)
                    acc[i][j] = fmaf(a[i], b[j], acc[i][j]);
        }
    }

    // Epilogue: scatter to g_q / g_k / g_v
#pragma unroll
    for (int i = 0; i < 4; i++) {
        int row = m0 + ty * 4 + i;
#pragma unroll
        for (int j = 0; j < 12; j++) {
            int c = tx * 12 + j;
            float* dst = (c < 64) ? g_q : ((c < 128) ? g_k : g_v);
            dst[row * H_ + (c & 63)] = acc[i][j];
        }
    }
}

// ---------------------------------------------------------------------------
// Kernel 2: causal flash attention, fp32, online softmax.
// One block per (batch, 64-row query tile); 256 threads; 4 threads per row,
// each owning a contiguous 16-column slice of scores AND a 16-wide slice of
// the output head dim. P is exchanged via smem (aliased over the K buffer).
// Heavy (high-qt) tiles are scheduled first to balance the causal wedge.
// ---------------------------------------------------------------------------
__global__ __launch_bounds__(256) void attn_kernel(float* __restrict__ out)
{
    __shared__ float Qs[64][64];
    __shared__ float Ks[64][64];   // reused as P[64][64] during PV phase
    __shared__ float Vs[64][64];

    const int t  = threadIdx.x;
    const int r  = t >> 2;          // row within tile: 0..63
    const int cg = (t & 3) * 16;    // this thread's 16-col group start

    const int bx = blockIdx.x;
    const int qt = (S_ / 64 - 1) - (bx >> 3);   // heaviest tiles first
    const int b  = bx & 7;
    const int q0 = qt * 64;
    const int base = b * S_;

    // Load Q tile (coalesced float4)
#pragma unroll
    for (int i = 0; i < 4; i++) {
        int f = t + 256 * i;                // float4 index over [64][16]
        int rr = f >> 4, hq = f & 15;
        *(float4*)(&Qs[rr][hq * 4]) =
            *(const float4*)(g_q + (base + q0 + rr) * H_ + hq * 4);
    }

    float o[16];
#pragma unroll
    for (int j = 0; j < 16; j++) o[j] = 0.f;
    float mrow = -1e30f, lrow = 0.f;
    const float scale = 0.03125f;   // D^-0.5 = 1/32 (embedding dim, per ref)

    for (int kt = 0; kt <= qt; kt++) {
        __syncthreads();   // previous iteration fully done with Ks/Vs
#pragma unroll
        for (int i = 0; i < 4; i++) {
            int f = t + 256 * i;
            int rr = f >> 4, hq = f & 15;
            int g = (base + kt * 64 + rr) * H_ + hq * 4;
            *(float4*)(&Ks[rr][hq * 4]) = *(const float4*)(g_k + g);
            *(float4*)(&Vs[rr][hq * 4]) = *(const float4*)(g_v + g);
        }
        __syncthreads();

        // Scores: s[j] = Q[r,:] . K[cg+j,:]   (float4 dot products)
        float s[16];
#pragma unroll
        for (int j = 0; j < 16; j++) s[j] = 0.f;
#pragma unroll 4
        for (int hq = 0; hq < 16; hq++) {
            float4 q4 = *(const float4*)(&Qs[r][hq * 4]);
#pragma unroll
            for (int j = 0; j < 16; j++) {
                float4 k4 = *(const float4*)(&Ks[cg + j][hq * 4]);
                s[j] = fmaf(q4.x, k4.x, s[j]);
                s[j] = fmaf(q4.y, k4.y, s[j]);
                s[j] = fmaf(q4.z, k4.z, s[j]);
                s[j] = fmaf(q4.w, k4.w, s[j]);
            }
        }

        // Scale + causal mask (mask only possible on the diagonal tile)
        float rowmax = -1e30f;
        if (kt == qt) {
#pragma unroll
            for (int j = 0; j < 16; j++) {
                float v = s[j] * scale;
                if (cg + j > r) v = -1e30f;
                s[j] = v;
                rowmax = fmaxf(rowmax, v);
            }
        } else {
#pragma unroll
            for (int j = 0; j < 16; j++) {
                float v = s[j] * scale;
                s[j] = v;
                rowmax = fmaxf(rowmax, v);
            }
        }
        // Row reduction across the 4 threads of this row (lanes differ in bits 0-1)
        rowmax = fmaxf(rowmax, __shfl_xor_sync(0xffffffffu, rowmax, 1));
        rowmax = fmaxf(rowmax, __shfl_xor_sync(0xffffffffu, rowmax, 2));

        float mnew  = fmaxf(mrow, rowmax);
        float alpha = __expf(mrow - mnew);
        float rsum  = 0.f;
#pragma unroll
        for (int j = 0; j < 16; j++) {
            float p = __expf(s[j] - mnew);
            s[j] = p;
            rsum += p;
        }
        rsum += __shfl_xor_sync(0xffffffffu, rsum, 1);
        rsum += __shfl_xor_sync(0xffffffffu, rsum, 2);
        lrow = lrow * alpha + rsum;
        mrow = mnew;
#pragma unroll
        for (int j = 0; j < 16; j++) o[j] *= alpha;

        __syncthreads();   // everyone finished reading Ks -> safe to alias as P
#pragma unroll
        for (int j = 0; j < 16; j += 4) {
            float4 p4 = make_float4(s[j], s[j + 1], s[j + 2], s[j + 3]);
            *(float4*)(&Ks[r][cg + j]) = p4;
        }
        __syncthreads();

        // PV: o[cg..cg+15] += sum_c P[r][c] * V[c][cg..cg+15]
#pragma unroll 8
        for (int c = 0; c < 64; c++) {
            float p = Ks[r][c];
#pragma unroll
            for (int jq = 0; jq < 4; jq++) {
                float4 v4 = *(const float4*)(&Vs[c][cg + jq * 4]);
                o[jq * 4 + 0] = fmaf(p, v4.x, o[jq * 4 + 0]);
                o[jq * 4 + 1] = fmaf(p, v4.y, o[jq * 4 + 1]);
                o[jq * 4 + 2] = fmaf(p, v4.z, o[jq * 4 + 2]);
                o[jq * 4 + 3] = fmaf(p, v4.w, o[jq * 4 + 3]);
            }
        }
    }

    float inv = 1.f / lrow;
#pragma unroll
    for (int jq = 0; jq < 4; jq++) {
        float4 v = make_float4(o[jq * 4 + 0] * inv, o[jq * 4 + 1] * inv,
                               o[jq * 4 + 2] * inv, o[jq * 4 + 3] * inv);
        *(float4*)(out + (base + q0 + r) * H_ + cg + jq * 4) = v;
    }
}

// ---------------------------------------------------------------------------
extern "C" void kernel_launch(void* const* d_in, const int* in_sizes, int n_in,
                              void* d_out, int out_size)
{
    (void)in_sizes; (void)n_in; (void)out_size;
    const float* x  = (const float*)d_in[0];   // idx [B,S,D]
    const float* Wk = (const float*)d_in[1];   // [D,H]
    const float* Wq = (const float*)d_in[2];   // [D,H]
    const float* Wv = (const float*)d_in[3];   // [D,H]
    float* out = (float*)d_out;                // [B,S,H] fp32

    proj_kernel<<<M_ / 64, 256>>>(x, Wq, Wk, Wv);
    attn_kernel<<<(S_ / 64) * B_, 256>>>(out);
}

// round 2
// speedup vs baseline: 2.7758x; 2.7758x over previous
#include <cuda_runtime.h>

#define B_ 8
#define S_ 2048
#define D_ 1024
#define H_ 64
#define M_ (B_*S_)

// Scratch for projected q, k, v ([B*S, H] row-major each)
__device__ float g_q[M_*H_];
__device__ float g_k[M_*H_];
__device__ float g_v[M_*H_];

// ---------------------------------------------------------------------------
// Kernel 1: fused QKV projection, register-blocked SGEMM.
// Block tile: 112 rows x 192 cols (q|k|v), 256 threads (16 tx x 16 ty).
// Thread tile: 7 rows x 12 cols (cols strided: c = tx + 16*j).
// x staged TRANSPOSED in smem so A-operands are warp broadcasts.
// Grid = 147 blocks ~= one balanced wave over 148 SMs.
// ---------------------------------------------------------------------------
#define KC 32
#define TM 112

__global__ __launch_bounds__(256, 2) void proj_kernel(
    const float* __restrict__ x,
    const float* __restrict__ Wq,
    const float* __restrict__ Wk,
    const float* __restrict__ Wv)
{
    __shared__ float xs[KC][TM + 4];   // [k][row] transposed (pad keeps 16B rows)
    __shared__ float ws[KC][196];      // [k][c], c = 0..191 over (q|k|v)

    const int t  = threadIdx.x;
    const int tx = t & 15;
    const int ty = t >> 4;
    const int m0 = blockIdx.x * TM;
    const int nrows = min(TM, M_ - m0);

    float acc[7][12];
#pragma unroll
    for (int i = 0; i < 7; i++)
#pragma unroll
        for (int j = 0; j < 12; j++) acc[i][j] = 0.f;

    for (int kk = 0; kk < D_; kk += KC) {
        __syncthreads();
        // Load x chunk [nrows x KC] -> xs transposed. float4 gmem reads.
        for (int f = t; f < TM * (KC / 4); f += 256) {
            int r  = f >> 3;            // row (KC/4 == 8 float4 per row)
            int kq = f & 7;
            if (r < nrows) {
                float4 v = *(const float4*)(x + (m0 + r) * D_ + kk + kq * 4);
                xs[kq * 4 + 0][r] = v.x;
                xs[kq * 4 + 1][r] = v.y;
                xs[kq * 4 + 2][r] = v.z;
                xs[kq * 4 + 3][r] = v.w;
            }
        }
        // Load W chunk: KC x 192 floats (48 float4 per k-row)
        for (int f = t; f < KC * 48; f += 256) {
            int k  = f / 48, c4 = f % 48;
            int mat = c4 >> 4, h4 = c4 & 15;
            const float* W = (mat == 0) ? Wq : ((mat == 1) ? Wk : Wv);
            float4 v = *(const float4*)(W + (kk + k) * H_ + h4 * 4);
            *(float4*)&ws[k][c4 * 4] = v;
        }
        __syncthreads();

#pragma unroll 8
        for (int k = 0; k < KC; k++) {
            float a[7], bb[12];
#pragma unroll
            for (int i = 0; i < 7; i++) a[i] = xs[k][ty * 7 + i];     // broadcast
#pragma unroll
            for (int j = 0; j < 12; j++) bb[j] = ws[k][tx + 16 * j];  // conflict-free
#pragma unroll
            for (int i = 0; i < 7; i++)
#pragma unroll
                for (int j = 0; j < 12; j++)
                    acc[i][j] = fmaf(a[i], bb[j], acc[i][j]);
        }
    }

    // Epilogue: c = tx + 16*j keeps warp writes h-contiguous per (i,j)
#pragma unroll
    for (int i = 0; i < 7; i++) {
        int r = ty * 7 + i;
        if (r < nrows) {
            int row = m0 + r;
#pragma unroll
            for (int j = 0; j < 12; j++) {
                int c = tx + 16 * j;
                float v = acc[i][j];
                if (c < 64)       g_q[row * H_ + c]        = v;
                else if (c < 128) g_k[row * H_ + (c - 64)] = v;
                else              g_v[row * H_ + (c - 128)] = v;
            }
        }
    }
}

// ---------------------------------------------------------------------------
// Kernel 2: causal flash attention, fp32, register-blocked 4x4 per thread.
// Block: one (batch, 64-row q-tile). 256 threads: tx=t&15 (k-col groups,
// strided c = tx+16j), ty=t>>4 (q-row groups, rows ty*4+i).
// Q and K tiles XOR-swizzled in smem (no padding -> 3 x 16KB = 48KB exactly).
// P (post-exp) aliases the K buffer, stored plain.
// Heavy q-tiles scheduled first; everything resident (3-4 blocks/SM).
// ---------------------------------------------------------------------------
__global__ __launch_bounds__(256) void attn_kernel(float* __restrict__ out)
{
    __shared__ float smQ[64 * 64];   // swizzled
    __shared__ float smKP[64 * 64];  // K swizzled; re-used as P (plain)
    __shared__ float smV[64 * 64];   // plain [c][h]

    const int t  = threadIdx.x;
    const int tx = t & 15;
    const int ty = t >> 4;

    const int bx = blockIdx.x;
    const int qt = (S_ / 64 - 1) - (bx >> 3);   // heaviest first
    const int b  = bx & 7;
    const int q0 = qt * 64;
    const int base = b * S_;

    // Load Q tile (swizzled: chunk h4 -> h4 ^ (row & 15))
#pragma unroll
    for (int i = 0; i < 4; i++) {
        int f = t + 256 * i;            // 1024 float4s
        int row = f >> 4, h4 = f & 15;
        float4 v = *(const float4*)(g_q + (base + q0 + row) * H_ + h4 * 4);
        *(float4*)&smQ[row * 64 + ((h4 ^ (row & 15)) << 2)] = v;
    }

    float s[4][4], o[4][4], m[4], l[4];
#pragma unroll
    for (int i = 0; i < 4; i++) {
        m[i] = -1e30f; l[i] = 0.f;
#pragma unroll
        for (int j = 0; j < 4; j++) o[i][j] = 0.f;
    }
    const float scale = 0.03125f;   // D^-0.5 = 1/32 (embedding dim, per ref)

    for (int kt = 0; kt <= qt; kt++) {
        __syncthreads();   // prior iter done with smKP/smV; also covers Q load
#pragma unroll
        for (int i = 0; i < 4; i++) {
            int f = t + 256 * i;
            int row = f >> 4, h4 = f & 15;
            int g = (base + kt * 64 + row) * H_ + h4 * 4;
            *(float4*)&smKP[row * 64 + ((h4 ^ (row & 15)) << 2)] =
                *(const float4*)(g_k + g);
            *(float4*)&smV[row * 64 + h4 * 4] = *(const float4*)(g_v + g);
        }
        __syncthreads();

        // ---- scores: s[i][j] = Q[row_i,:] . K[col_j,:] ----
#pragma unroll
        for (int i = 0; i < 4; i++)
#pragma unroll
            for (int j = 0; j < 4; j++) s[i][j] = 0.f;

#pragma unroll 4
        for (int hq = 0; hq < 16; hq++) {
            float4 q[4], kf[4];
#pragma unroll
            for (int i = 0; i < 4; i++) {
                int r = ty * 4 + i;
                q[i] = *(const float4*)&smQ[r * 64 + ((hq ^ (r & 15)) << 2)];
            }
#pragma unroll
            for (int j = 0; j < 4; j++) {
                int c = tx + 16 * j;
                kf[j] = *(const float4*)&smKP[c * 64 + ((hq ^ (c & 15)) << 2)];
            }
#pragma unroll
            for (int i = 0; i < 4; i++)
#pragma unroll
                for (int j = 0; j < 4; j++) {
                    s[i][j] = fmaf(q[i].x, kf[j].x, s[i][j]);
                    s[i][j] = fmaf(q[i].y, kf[j].y, s[i][j]);
                    s[i][j] = fmaf(q[i].z, kf[j].z, s[i][j]);
                    s[i][j] = fmaf(q[i].w, kf[j].w, s[i][j]);
                }
        }

        // ---- mask + online softmax (per owned row i) ----
        const bool diag = (kt == qt);
#pragma unroll
        for (int i = 0; i < 4; i++) {
            int r = ty * 4 + i;
            float rmax = -1e30f;
#pragma unroll
            for (int j = 0; j < 4; j++) {
                float v = s[i][j] * scale;
                if (diag && (tx + 16 * j) > r) v = -1e30f;
                s[i][j] = v;
                rmax = fmaxf(rmax, v);
            }
            rmax = fmaxf(rmax, __shfl_xor_sync(0xffffffffu, rmax, 1));
            rmax = fmaxf(rmax, __shfl_xor_sync(0xffffffffu, rmax, 2));
            rmax = fmaxf(rmax, __shfl_xor_sync(0xffffffffu, rmax, 4));
            rmax = fmaxf(rmax, __shfl_xor_sync(0xffffffffu, rmax, 8));

            float mn    = fmaxf(m[i], rmax);
            float alpha = __expf(m[i] - mn);
            m[i] = mn;
            float rs = 0.f;
#pragma unroll
            for (int j = 0; j < 4; j++) {
                float p = __expf(s[i][j] - mn);
                s[i][j] = p;
                rs += p;
            }
            rs += __shfl_xor_sync(0xffffffffu, rs, 1);
            rs += __shfl_xor_sync(0xffffffffu, rs, 2);
            rs += __shfl_xor_sync(0xffffffffu, rs, 4);
            rs += __shfl_xor_sync(0xffffffffu, rs, 8);
            l[i] = l[i] * alpha + rs;
#pragma unroll
            for (int j = 0; j < 4; j++) o[i][j] *= alpha;
        }

        __syncthreads();   // all done reading K -> safe to overwrite as P
#pragma unroll
        for (int i = 0; i < 4; i++)
#pragma unroll
            for (int j = 0; j < 4; j++)
                smKP[(ty * 4 + i) * 64 + tx + 16 * j] = s[i][j];
        __syncthreads();

        // ---- PV: o[i][j] += sum_c P[row_i][c] * V[c][h_j] ----
#pragma unroll 4
        for (int c4 = 0; c4 < 16; c4++) {
            float4 p[4];
#pragma unroll
            for (int i = 0; i < 4; i++)
                p[i] = *(const float4*)&smKP[(ty * 4 + i) * 64 + c4 * 4];  // bcast
#pragma unroll
            for (int cc = 0; cc < 4; cc++) {
                float v[4];
#pragma unroll
                for (int j = 0; j < 4; j++)
                    v[j] = smV[(c4 * 4 + cc) * 64 + tx + 16 * j];
                float pc;
#pragma unroll
                for (int i = 0; i < 4; i++) {
                    pc = (cc == 0) ? p[i].x : (cc == 1) ? p[i].y
                                   : (cc == 2) ? p[i].z : p[i].w;
#pragma unroll
                    for (int j = 0; j < 4; j++)
                        o[i][j] = fmaf(pc, v[j], o[i][j]);
                }
            }
        }
    }

    // ---- normalize + write ----
#pragma unroll
    for (int i = 0; i < 4; i++) {
        float inv = 1.f / l[i];
        int row = base + q0 + ty * 4 + i;
#pragma unroll
        for (int j = 0; j < 4; j++)
            out[row * H_ + tx + 16 * j] = o[i][j] * inv;
    }
}

// ---------------------------------------------------------------------------
extern "C" void kernel_launch(void* const* d_in, const int* in_sizes, int n_in,
                              void* d_out, int out_size)
{
    (void)in_sizes; (void)n_in; (void)out_size;
    const float* x  = (const float*)d_in[0];   // idx [B,S,D]
    const float* Wk = (const float*)d_in[1];   // [D,H]
    const float* Wq = (const float*)d_in[2];   // [D,H]
    const float* Wv = (const float*)d_in[3];   // [D,H]
    float* out = (float*)d_out;                // [B,S,H] fp32

    proj_kernel<<<(M_ + TM - 1) / TM, 256>>>(x, Wq, Wk, Wv);
    attn_kernel<<<(S_ / 64) * B_, 256>>>(out);
}